// round 6
// baseline (speedup 1.0000x reference)
#include <cuda_runtime.h>
#include <cuda_bf16.h>
#include <math.h>
#include <stdint.h>

// Problem constants
#define BB 2
#define SS 2048
#define DIN 1024
#define HH 16
#define DKK 1024
#define DVV 1024
#define DOUT 1024
#define MROWS (BB*SS)          // 4096
#define BH (BB*HH)             // 32
#define HEADV 64
#define SCALE 0.125f
#define LN_EPS 1e-5f

// Scratch
__device__ float g_q  [(size_t)MROWS * DKK];
__device__ float g_k  [(size_t)MROWS * DKK];
__device__ float g_v  [(size_t)MROWS * DVV];
__device__ float g_ctx[(size_t)MROWS * DVV];
__device__ float g_res[(size_t)MROWS * DOUT];
__device__ float g_cb [(size_t)MROWS * HH];
__device__ float g_cbt[(size_t)BH * SS];
__device__ __nv_bfloat16 g_qh[(size_t)BH * SS * DKK];
__device__ __nv_bfloat16 g_ql[(size_t)BH * SS * DKK];
__device__ __nv_bfloat16 g_kh[(size_t)MROWS * DKK];
__device__ __nv_bfloat16 g_kl[(size_t)MROWS * DKK];
__device__ __nv_bfloat16 g_xh[(size_t)MROWS * DIN];
__device__ __nv_bfloat16 g_xl[(size_t)MROWS * DIN];
__device__ __nv_bfloat16 g_wh[(size_t)4 * 1024 * 1024];
__device__ __nv_bfloat16 g_wl[(size_t)4 * 1024 * 1024];
__device__ __nv_bfloat16 g_vth[(size_t)BH * HEADV * SS];
__device__ __nv_bfloat16 g_vtl[(size_t)BH * HEADV * SS];
__device__ __nv_bfloat16 g_cxh[(size_t)MROWS * DVV];
__device__ __nv_bfloat16 g_cxl[(size_t)MROWS * DVV];

// ======================= helpers ===========================================
__device__ __forceinline__ uint32_t smem_to_u32(const void* p) {
    uint32_t a;
    asm("{ .reg .u64 t; cvta.to.shared.u64 t, %1; cvt.u32.u64 %0, t; }" : "=r"(a) : "l"(p));
    return a;
}
__device__ __forceinline__ void cp16(uint32_t s, const void* g) {
    asm volatile("cp.async.cg.shared.global [%0], [%1], 16;" :: "r"(s), "l"(g));
}
#define CP_COMMIT() asm volatile("cp.async.commit_group;" ::: "memory")
#define CP_WAIT1()  asm volatile("cp.async.wait_group 1;" ::: "memory")
#define CP_WAIT0()  asm volatile("cp.async.wait_group 0;" ::: "memory")

__device__ __forceinline__ void ldsm_x4(uint32_t* r, uint32_t addr) {
    asm volatile("ldmatrix.sync.aligned.m8n8.x4.shared.b16 {%0,%1,%2,%3}, [%4];"
        : "=r"(r[0]), "=r"(r[1]), "=r"(r[2]), "=r"(r[3]) : "r"(addr));
}
__device__ __forceinline__ void ldsm_x2(uint32_t* r, uint32_t addr) {
    asm volatile("ldmatrix.sync.aligned.m8n8.x2.shared.b16 {%0,%1}, [%2];"
        : "=r"(r[0]), "=r"(r[1]) : "r"(addr));
}
__device__ __forceinline__ void mma_bf16(float* c, const uint32_t* a, const uint32_t* b) {
    asm volatile("mma.sync.aligned.m16n8k16.row.col.f32.bf16.bf16.f32 "
        "{%0,%1,%2,%3}, {%4,%5,%6,%7}, {%8,%9}, {%0,%1,%2,%3};"
        : "+f"(c[0]), "+f"(c[1]), "+f"(c[2]), "+f"(c[3])
        : "r"(a[0]), "r"(a[1]), "r"(a[2]), "r"(a[3]), "r"(b[0]), "r"(b[1]));
}
__device__ __forceinline__ uint32_t pack2(__nv_bfloat16 a, __nv_bfloat16 b) {
    return (uint32_t)__bfloat16_as_ushort(a) | ((uint32_t)__bfloat16_as_ushort(b) << 16);
}

// ======================= generic fp32 -> bf16 hi/lo split ==================
__global__ __launch_bounds__(256)
void split_kernel(const float* __restrict__ in,
                  __nv_bfloat16* __restrict__ h, __nv_bfloat16* __restrict__ l)
{
    const size_t i4 = (size_t)blockIdx.x * 256 + threadIdx.x;
    float4 v = *(const float4*)(in + i4 * 4);
    __nv_bfloat16 h0 = __float2bfloat16(v.x), h1 = __float2bfloat16(v.y);
    __nv_bfloat16 h2 = __float2bfloat16(v.z), h3 = __float2bfloat16(v.w);
    uint2 hp, lp;
    hp.x = pack2(h0, h1); hp.y = pack2(h2, h3);
    lp.x = pack2(__float2bfloat16(v.x - __bfloat162float(h0)),
                 __float2bfloat16(v.y - __bfloat162float(h1)));
    lp.y = pack2(__float2bfloat16(v.z - __bfloat162float(h2)),
                 __float2bfloat16(v.w - __bfloat162float(h3)));
    *(uint2*)(h + i4 * 4) = hp;
    *(uint2*)(l + i4 * 4) = lp;
}

// ======================= small fp32 GEMM (content bias only) ===============
__global__ __launch_bounds__(256)
void gemm_nt_kernel(const float* __restrict__ A, const float* __restrict__ W,
                    float* __restrict__ out, int M, int N, int K)
{
    __shared__ float As[16][68];
    __shared__ float Ws[16][68];
    const int tid = threadIdx.x;
    const int m0 = blockIdx.y * 64;
    const int lr = tid >> 2, lc = (tid & 3) * 4;
    const int ty = tid >> 4, tx = tid & 15;

    float acc[4][4];
#pragma unroll
    for (int r = 0; r < 4; r++)
#pragma unroll
        for (int c = 0; c < 4; c++) acc[r][c] = 0.f;

    const float* Aptr = A + (size_t)(m0 + lr) * K + lc;
    const int n = lr;
    const float* Wptr = W + (size_t)n * K + lc;
    const bool nok = (n < N);

    for (int k0 = 0; k0 < K; k0 += 16) {
        float4 a = *(const float4*)(Aptr + k0);
        float4 w = make_float4(0.f, 0.f, 0.f, 0.f);
        if (nok) w = *(const float4*)(Wptr + k0);
        __syncthreads();
        As[lc + 0][lr] = a.x; As[lc + 1][lr] = a.y; As[lc + 2][lr] = a.z; As[lc + 3][lr] = a.w;
        Ws[lc + 0][lr] = w.x; Ws[lc + 1][lr] = w.y; Ws[lc + 2][lr] = w.z; Ws[lc + 3][lr] = w.w;
        __syncthreads();
#pragma unroll
        for (int kk = 0; kk < 16; kk++) {
            float4 av = *(const float4*)&As[kk][ty * 4];
            float4 wv = *(const float4*)&Ws[kk][tx * 4];
            acc[0][0] += av.x * wv.x; acc[0][1] += av.x * wv.y; acc[0][2] += av.x * wv.z; acc[0][3] += av.x * wv.w;
            acc[1][0] += av.y * wv.x; acc[1][1] += av.y * wv.y; acc[1][2] += av.y * wv.z; acc[1][3] += av.y * wv.w;
            acc[2][0] += av.z * wv.x; acc[2][1] += av.z * wv.y; acc[2][2] += av.z * wv.z; acc[2][3] += av.z * wv.w;
            acc[3][0] += av.w * wv.x; acc[3][1] += av.w * wv.y; acc[3][2] += av.w * wv.z; acc[3][3] += av.w * wv.w;
        }
    }
#pragma unroll
    for (int r = 0; r < 4; r++) {
        const int m = m0 + ty * 4 + r;
#pragma unroll
        for (int c = 0; c < 4; c++) {
            const int nn = tx * 4 + c;
            if (nn < N) out[(size_t)m * N + nn] = acc[r][c];
        }
    }
}

// ======================= generic HMMA NT GEMM (projections) ================
#define PJ_STAGE 65536
#define PJ_AH 0
#define PJ_AL 16384
#define PJ_BH 32768
#define PJ_BL 49152
#define PJ_NST 16

__global__ __launch_bounds__(256, 1)
void hmma_nt_kernel(const __nv_bfloat16* __restrict__ Ahp, const __nv_bfloat16* __restrict__ Alp,
                    const __nv_bfloat16* __restrict__ Bhp, const __nv_bfloat16* __restrict__ Blp,
                    const float* __restrict__ bias, const float* __restrict__ resid,
                    float* __restrict__ C, int N)
{
    extern __shared__ __align__(1024) char smem[];
    const uint32_t sb = smem_to_u32(smem);

    const int tid = threadIdx.x;
    const int wid = tid >> 5;
    const int lane = tid & 31;
    const int m0 = blockIdx.y * 128;
    const int n0 = blockIdx.x * 128;
    const int warp_m = wid >> 2;
    const int warp_n = wid & 3;

    const __nv_bfloat16* Ah_b = Ahp + (size_t)m0 * DKK;
    const __nv_bfloat16* Al_b = Alp + (size_t)m0 * DKK;
    const __nv_bfloat16* Bh_b = Bhp + (size_t)n0 * DKK;
    const __nv_bfloat16* Bl_b = Blp + (size_t)n0 * DKK;

    float acc[4][4][4];
#pragma unroll
    for (int mt = 0; mt < 4; mt++)
#pragma unroll
        for (int nt = 0; nt < 4; nt++)
#pragma unroll
            for (int e = 0; e < 4; e++) acc[mt][nt][e] = 0.f;

    int cso[4];
    size_t cgi[4];
#pragma unroll
    for (int r = 0; r < 4; r++) {
        const int chunk = tid + 256 * r;
        const int row = chunk >> 3;
        const int cc = chunk & 7;
        cso[r] = row * 128 + ((cc * 16) ^ ((row & 7) << 4));
        cgi[r] = (size_t)row * DKK + cc * 8;
    }

    const int rowA = warp_m * 64 + (lane & 15);
    const int colA = ((lane >> 4) << 4);
    const uint32_t maskA = (rowA & 7) << 4;
    const int rowB = warp_n * 32 + (lane & 7);
    const int colB = ((lane >> 3) & 1) << 4;
    const uint32_t maskB = (rowB & 7) << 4;

    {
        const uint32_t st = sb;
#pragma unroll
        for (int r = 0; r < 4; r++) {
            cp16(st + PJ_AH + cso[r], Ah_b + cgi[r]);
            cp16(st + PJ_AL + cso[r], Al_b + cgi[r]);
            cp16(st + PJ_BH + cso[r], Bh_b + cgi[r]);
            cp16(st + PJ_BL + cso[r], Bl_b + cgi[r]);
        }
        CP_COMMIT();
    }

    for (int s = 0; s < PJ_NST; s++) {
        if (s + 1 < PJ_NST) {
            const uint32_t st = sb + ((s + 1) & 1) * PJ_STAGE;
            const size_t koff = (size_t)(s + 1) * 64;
#pragma unroll
            for (int r = 0; r < 4; r++) {
                cp16(st + PJ_AH + cso[r], Ah_b + cgi[r] + koff);
                cp16(st + PJ_AL + cso[r], Al_b + cgi[r] + koff);
                cp16(st + PJ_BH + cso[r], Bh_b + cgi[r] + koff);
                cp16(st + PJ_BL + cso[r], Bl_b + cgi[r] + koff);
            }
            CP_COMMIT();
            CP_WAIT1();
        } else {
            CP_WAIT0();
        }
        __syncthreads();

        const uint32_t st = sb + (s & 1) * PJ_STAGE;
#pragma unroll
        for (int ks = 0; ks < 4; ks++) {
            const int k0b = ks * 32;
            uint32_t Ahf[4][4], Alf[4][4], Bhf[4][2], Blf[4][2];
#pragma unroll
            for (int mt = 0; mt < 4; mt++)
                ldsm_x4(Ahf[mt], st + PJ_AH + (uint32_t)((rowA + mt * 16) * 128) + (uint32_t)((k0b + colA) ^ maskA));
#pragma unroll
            for (int nt = 0; nt < 4; nt++) {
                ldsm_x2(Bhf[nt], st + PJ_BH + (uint32_t)((rowB + nt * 8) * 128) + (uint32_t)((k0b + colB) ^ maskB));
                ldsm_x2(Blf[nt], st + PJ_BL + (uint32_t)((rowB + nt * 8) * 128) + (uint32_t)((k0b + colB) ^ maskB));
            }
#pragma unroll
            for (int mt = 0; mt < 4; mt++)
#pragma unroll
                for (int nt = 0; nt < 4; nt++)
                    mma_bf16(acc[mt][nt], Ahf[mt], Bhf[nt]);
#pragma unroll
            for (int mt = 0; mt < 4; mt++)
                ldsm_x4(Alf[mt], st + PJ_AL + (uint32_t)((rowA + mt * 16) * 128) + (uint32_t)((k0b + colA) ^ maskA));
#pragma unroll
            for (int mt = 0; mt < 4; mt++)
#pragma unroll
                for (int nt = 0; nt < 4; nt++)
                    mma_bf16(acc[mt][nt], Ahf[mt], Blf[nt]);
#pragma unroll
            for (int mt = 0; mt < 4; mt++)
#pragma unroll
                for (int nt = 0; nt < 4; nt++)
                    mma_bf16(acc[mt][nt], Alf[mt], Bhf[nt]);
        }
        __syncthreads();
    }

    const int r0 = lane >> 2;
    const int c0 = (lane & 3) * 2;
#pragma unroll
    for (int mt = 0; mt < 4; mt++) {
        const int mrow = m0 + warp_m * 64 + mt * 16 + r0;
#pragma unroll
        for (int nt = 0; nt < 4; nt++) {
            const int ncol = n0 + warp_n * 32 + nt * 8 + c0;
#pragma unroll
            for (int half = 0; half < 2; half++) {
                const int m = mrow + half * 8;
                float2 v = half ? make_float2(acc[mt][nt][2], acc[mt][nt][3])
                                : make_float2(acc[mt][nt][0], acc[mt][nt][1]);
                if (bias)  { v.x += bias[ncol]; v.y += bias[ncol + 1]; }
                if (resid) {
                    float2 rr = *(const float2*)(resid + (size_t)m * N + ncol);
                    v.x += rr.x; v.y += rr.y;
                }
                *(float2*)(C + (size_t)m * N + ncol) = v;
            }
        }
    }
}

// ======================= prep q (fold mixing*scale) ========================
__global__ __launch_bounds__(256)
void prep_q_kernel(const float* __restrict__ q, const float* __restrict__ mixing,
                   __nv_bfloat16* __restrict__ qh, __nv_bfloat16* __restrict__ ql)
{
    const int bh = blockIdx.y;
    const int b = bh >> 4, h = bh & 15;
    const size_t i4 = (size_t)blockIdx.x * 256 + threadIdx.x;
    const int s = (int)(i4 >> 8);
    const int c4 = (int)(i4 & 255);
    float4 v = *(const float4*)(q + ((size_t)b * SS + s) * DKK + c4 * 4);
    float4 m = *(const float4*)(mixing + (size_t)h * DKK + c4 * 4);
    v.x *= m.x * SCALE; v.y *= m.y * SCALE; v.z *= m.z * SCALE; v.w *= m.w * SCALE;
    __nv_bfloat16 h0 = __float2bfloat16(v.x), h1 = __float2bfloat16(v.y);
    __nv_bfloat16 h2 = __float2bfloat16(v.z), h3 = __float2bfloat16(v.w);
    uint2 hp, lp;
    hp.x = pack2(h0, h1); hp.y = pack2(h2, h3);
    lp.x = pack2(__float2bfloat16(v.x - __bfloat162float(h0)),
                 __float2bfloat16(v.y - __bfloat162float(h1)));
    lp.y = pack2(__float2bfloat16(v.z - __bfloat162float(h2)),
                 __float2bfloat16(v.w - __bfloat162float(h3)));
    const size_t o = ((size_t)bh * SS + s) * DKK + c4 * 4;
    *(uint2*)(qh + o) = hp;
    *(uint2*)(ql + o) = lp;
}

// ======================= prep V^T per head (bf16 hi/lo) ====================
__global__ __launch_bounds__(256)
void prep_vt_kernel(const float* __restrict__ v,
                    __nv_bfloat16* __restrict__ vth, __nv_bfloat16* __restrict__ vtl)
{
    const int tid = threadIdx.x;
    const int bh = blockIdx.z;
    const int b = bh >> 4, h = bh & 15;
    const int j = blockIdx.x * 64 + (tid & 63);
    const int vvg = blockIdx.y * 4 + (tid >> 6);
    float4 v4 = *(const float4*)(v + ((size_t)b * SS + j) * DVV + h * HEADV + vvg * 4);
#pragma unroll
    for (int e = 0; e < 4; e++) {
        float val = (&v4.x)[e];
        __nv_bfloat16 hh = __float2bfloat16(val);
        __nv_bfloat16 ll = __float2bfloat16(val - __bfloat162float(hh));
        const size_t o = ((size_t)bh * HEADV + vvg * 4 + e) * SS + j;
        vth[o] = hh; vtl[o] = ll;
    }
}

__global__ __launch_bounds__(256)
void cbt_kernel(const float* __restrict__ cb, float* __restrict__ cbt)
{
    const int bh = blockIdx.y;
    const int b = bh >> 4, h = bh & 15;
    const int j = blockIdx.x * 256 + threadIdx.x;
    cbt[(size_t)bh * SS + j] = cb[((size_t)b * SS + j) * HH + h] * SCALE;
}

// ======================= fully fused flash attention =======================
// CTA: 128 q-rows x full S, one bh.  Per 256-j tile:
//   QK^T 3-pass HMMA (128x256, K=1024 double-buffered) -> online softmax
//   -> P hi/lo into (reused) stage smem -> PV 3-pass HMMA into O regs.
#define FL_AH 0
#define FL_AL 16384
#define FL_BH 32768
#define FL_BL 65536
#define FL_STAGE 98304          // 96 KB per stage, 2 stages
#define FL_PH 0                 // P hi: 128 rows x 512B  (reuses stage area)
#define FL_PL 65536             // P lo: 64 KB
#define FL_V  131072            // V: 2 chunks x (16KB hi + 16KB lo) = 64 KB
#define FL_STATS 196608         // partial max/sum [128][4] = 2 KB (reused)
#define FL_M   198656           // m_run[128]
#define FL_L   199168           // l_run[128]
#define FL_SCL 199680           // scl[128]
#define FL_SMEM 200192
#define FL_NST 16

__global__ __launch_bounds__(256, 1)
void flash_kernel(const __nv_bfloat16* __restrict__ qh, const __nv_bfloat16* __restrict__ ql,
                  const __nv_bfloat16* __restrict__ kh, const __nv_bfloat16* __restrict__ kl,
                  const float* __restrict__ cbt,
                  const __nv_bfloat16* __restrict__ vth, const __nv_bfloat16* __restrict__ vtl,
                  float* __restrict__ ctx)
{
    extern __shared__ __align__(1024) char sm[];
    const uint32_t sb = smem_to_u32(sm);
    float* sm_stat = (float*)(sm + FL_STATS);
    float* sm_m    = (float*)(sm + FL_M);
    float* sm_l    = (float*)(sm + FL_L);
    float* sm_scl  = (float*)(sm + FL_SCL);

    const int tid = threadIdx.x;
    const int wid = tid >> 5;
    const int lane = tid & 31;
    const int bh = blockIdx.y;
    const int b = bh >> 4, h = bh & 15;
    const int i0 = blockIdx.x * 128;
    const int warp_m = wid >> 2;     // 0..1
    const int warp_n = wid & 3;      // 0..3

    const __nv_bfloat16* qh_b = qh + ((size_t)bh * SS + i0) * DKK;
    const __nv_bfloat16* ql_b = ql + ((size_t)bh * SS + i0) * DKK;

    if (tid < 128) { sm_m[tid] = -INFINITY; sm_l[tid] = 0.f; }

    float O[8][4];
#pragma unroll
    for (int nn = 0; nn < 8; nn++)
#pragma unroll
        for (int e = 0; e < 4; e++) O[nn][e] = 0.f;

    int csoA[4];  size_t cgiA[4];
#pragma unroll
    for (int r = 0; r < 4; r++) {
        const int chunk = tid + 256 * r;
        const int row = chunk >> 3, cc = chunk & 7;
        csoA[r] = row * 128 + ((cc * 16) ^ ((row & 7) << 4));
        cgiA[r] = (size_t)row * DKK + cc * 8;
    }
    int csoB[8];  size_t cgiB[8];
#pragma unroll
    for (int r = 0; r < 8; r++) {
        const int chunk = tid + 256 * r;
        const int row = chunk >> 3, cc = chunk & 7;
        csoB[r] = row * 128 + ((cc * 16) ^ ((row & 7) << 4));
        cgiB[r] = (size_t)row * DKK + cc * 8;
    }

    __syncthreads();

    for (int j0 = 0; j0 < SS; j0 += 256) {
        const __nv_bfloat16* kh_b = kh + ((size_t)b * SS + j0) * DKK;
        const __nv_bfloat16* kl_b = kl + ((size_t)b * SS + j0) * DKK;

        float acc[4][8][4];
#pragma unroll
        for (int mt = 0; mt < 4; mt++)
#pragma unroll
            for (int nn = 0; nn < 8; nn++)
#pragma unroll
                for (int e = 0; e < 4; e++) acc[mt][nn][e] = 0.f;

        // ---- QK^T over K=1024, double-buffered -------------------------
        {
            const uint32_t st = sb;
#pragma unroll
            for (int r = 0; r < 4; r++) {
                cp16(st + FL_AH + csoA[r], qh_b + cgiA[r]);
                cp16(st + FL_AL + csoA[r], ql_b + cgiA[r]);
            }
#pragma unroll
            for (int r = 0; r < 8; r++) {
                cp16(st + FL_BH + csoB[r], kh_b + cgiB[r]);
                cp16(st + FL_BL + csoB[r], kl_b + cgiB[r]);
            }
            CP_COMMIT();
        }

        for (int s = 0; s < FL_NST; s++) {
            if (s + 1 < FL_NST) {
                const uint32_t st = sb + ((s + 1) & 1) * FL_STAGE;
                const size_t koff = (size_t)(s + 1) * 64;
#pragma unroll
                for (int r = 0; r < 4; r++) {
                    cp16(st + FL_AH + csoA[r], qh_b + cgiA[r] + koff);
                    cp16(st + FL_AL + csoA[r], ql_b + cgiA[r] + koff);
                }
#pragma unroll
                for (int r = 0; r < 8; r++) {
                    cp16(st + FL_BH + csoB[r], kh_b + cgiB[r] + koff);
                    cp16(st + FL_BL + csoB[r], kl_b + cgiB[r] + koff);
                }
                CP_COMMIT();
                CP_WAIT1();
            } else {
                CP_WAIT0();
            }
            __syncthreads();

            const uint32_t st = sb + (s & 1) * FL_STAGE;
#pragma unroll
            for (int ks = 0; ks < 4; ks++) {
                const int k0b = ks * 32;
                uint32_t Ahf[4][4], Alf[4][4];
#pragma unroll
                for (int mt = 0; mt < 4; mt++) {
                    const int rowA = warp_m * 64 + mt * 16 + (lane & 15);
                    const uint32_t cA = (uint32_t)((k0b + ((lane >> 4) << 4)) ^ ((rowA & 7) << 4));
                    ldsm_x4(Ahf[mt], st + FL_AH + (uint32_t)(rowA * 128) + cA);
                    ldsm_x4(Alf[mt], st + FL_AL + (uint32_t)(rowA * 128) + cA);
                }
#pragma unroll
                for (int ng = 0; ng < 4; ng++) {
                    const int rowB = warp_n * 64 + ng * 16 + (lane & 7) + ((lane & 16) >> 1);
                    const uint32_t cB = (uint32_t)((k0b + (((lane >> 3) & 1) << 4)) ^ ((rowB & 7) << 4));
                    uint32_t Bh4[4], Bl4[4];
                    ldsm_x4(Bh4, st + FL_BH + (uint32_t)(rowB * 128) + cB);
#pragma unroll
                    for (int mt = 0; mt < 4; mt++) {
                        mma_bf16(acc[mt][ng * 2 + 0], Ahf[mt], Bh4 + 0);
                        mma_bf16(acc[mt][ng * 2 + 1], Ahf[mt], Bh4 + 2);
                        mma_bf16(acc[mt][ng * 2 + 0], Alf[mt], Bh4 + 0);
                        mma_bf16(acc[mt][ng * 2 + 1], Alf[mt], Bh4 + 2);
                    }
                    ldsm_x4(Bl4, st + FL_BL + (uint32_t)(rowB * 128) + cB);
#pragma unroll
                    for (int mt = 0; mt < 4; mt++) {
                        mma_bf16(acc[mt][ng * 2 + 0], Ahf[mt], Bl4 + 0);
                        mma_bf16(acc[mt][ng * 2 + 1], Ahf[mt], Bl4 + 2);
                    }
                }
            }
            __syncthreads();
        }

        // ---- V prefetch into freed stage smem --------------------------
#pragma unroll
        for (int c = 0; c < 2; c++) {
#pragma unroll
            for (int r = 0; r < 4; r++) {
                const int id = tid + 256 * r;
                const int row = id >> 4, cc = id & 15;
                const uint32_t so = (uint32_t)(row * 256 + ((cc * 16) ^ ((row & 7) << 4)));
                const size_t gi = ((size_t)bh * HEADV + row) * SS + j0 + c * 128 + cc * 8;
                cp16(sb + FL_V + c * 32768 + so, vth + gi);
                cp16(sb + FL_V + c * 32768 + 16384 + so, vtl + gi);
            }
        }
        CP_COMMIT();

        // ---- add content bias, row max --------------------------------
        const float* cbp = cbt + (size_t)bh * SS + j0;
        float rmax[8];
#pragma unroll
        for (int i = 0; i < 8; i++) rmax[i] = -INFINITY;
#pragma unroll
        for (int nn = 0; nn < 8; nn++) {
            float2 cb2 = *(const float2*)(cbp + warp_n * 64 + nn * 8 + (lane & 3) * 2);
#pragma unroll
            for (int mt = 0; mt < 4; mt++) {
                acc[mt][nn][0] += cb2.x; acc[mt][nn][1] += cb2.y;
                acc[mt][nn][2] += cb2.x; acc[mt][nn][3] += cb2.y;
                rmax[mt * 2 + 0] = fmaxf(rmax[mt * 2 + 0], fmaxf(acc[mt][nn][0], acc[mt][nn][1]));
                rmax[mt * 2 + 1] = fmaxf(rmax[mt * 2 + 1], fmaxf(acc[mt][nn][2], acc[mt][nn][3]));
            }
        }
#pragma unroll
        for (int i = 0; i < 8; i++) {
            rmax[i] = fmaxf(rmax[i], __shfl_xor_sync(0xffffffffu, rmax[i], 1));
            rmax[i] = fmaxf(rmax[i], __shfl_xor_sync(0xffffffffu, rmax[i], 2));
        }
        if ((lane & 3) == 0) {
#pragma unroll
            for (int mt = 0; mt < 4; mt++) {
                const int r = warp_m * 64 + mt * 16 + (lane >> 2);
                sm_stat[(r + 0) * 4 + warp_n] = rmax[mt * 2 + 0];
                sm_stat[(r + 8) * 4 + warp_n] = rmax[mt * 2 + 1];
            }
        }
        __syncthreads();
        if (tid < 128) {
            float mx = fmaxf(fmaxf(sm_stat[tid * 4 + 0], sm_stat[tid * 4 + 1]),
                             fmaxf(sm_stat[tid * 4 + 2], sm_stat[tid * 4 + 3]));
            const float mold = sm_m[tid];
            const float mnew = fmaxf(mold, mx);
            sm_m[tid] = mnew;
            sm_scl[tid] = __expf(mold - mnew);
        }
        __syncthreads();

        // ---- exp, P store (hi/lo), partial sums ------------------------
        float rsum[8];
#pragma unroll
        for (int i = 0; i < 8; i++) rsum[i] = 0.f;
#pragma unroll
        for (int mt = 0; mt < 4; mt++) {
            const int r0 = warp_m * 64 + mt * 16 + (lane >> 2);
            const float mn0 = sm_m[r0];
            const float mn1 = sm_m[r0 + 8];
            const uint32_t off0base = (uint32_t)(r0 * 512);
            const uint32_t off1base = (uint32_t)((r0 + 8) * 512);
            const uint32_t mask0 = (uint32_t)((r0 & 7) << 4);
            const uint32_t mask1 = (uint32_t)(((r0 + 8) & 7) << 4);
#pragma unroll
            for (int nn = 0; nn < 8; nn++) {
                float p0 = __expf(acc[mt][nn][0] - mn0);
                float p1 = __expf(acc[mt][nn][1] - mn0);
                float p2 = __expf(acc[mt][nn][2] - mn1);
                float p3 = __expf(acc[mt][nn][3] - mn1);
                rsum[mt * 2 + 0] += p0 + p1;
                rsum[mt * 2 + 1] += p2 + p3;
                const uint32_t colbyte = (uint32_t)((warp_n * 64 + nn * 8 + (lane & 3) * 2) * 2);
                __nv_bfloat16 h0 = __float2bfloat16(p0), h1 = __float2bfloat16(p1);
                __nv_bfloat16 h2 = __float2bfloat16(p2), h3 = __float2bfloat16(p3);
                const uint32_t o0 = off0base + (colbyte ^ mask0);
                const uint32_t o1 = off1base + (colbyte ^ mask1);
                *(uint32_t*)(sm + FL_PH + o0) = pack2(h0, h1);
                *(uint32_t*)(sm + FL_PH + o1) = pack2(h2, h3);
                *(uint32_t*)(sm + FL_PL + o0) = pack2(__float2bfloat16(p0 - __bfloat162float(h0)),
                                                      __float2bfloat16(p1 - __bfloat162float(h1)));
                *(uint32_t*)(sm + FL_PL + o1) = pack2(__float2bfloat16(p2 - __bfloat162float(h2)),
                                                      __float2bfloat16(p3 - __bfloat162float(h3)));
            }
        }
#pragma unroll
        for (int i = 0; i < 8; i++) {
            rsum[i] += __shfl_xor_sync(0xffffffffu, rsum[i], 1);
            rsum[i] += __shfl_xor_sync(0xffffffffu, rsum[i], 2);
        }
        if ((lane & 3) == 0) {
#pragma unroll
            for (int mt = 0; mt < 4; mt++) {
                const int r = warp_m * 64 + mt * 16 + (lane >> 2);
                sm_stat[(r + 0) * 4 + warp_n] = rsum[mt * 2 + 0];
                sm_stat[(r + 8) * 4 + warp_n] = rsum[mt * 2 + 1];
            }
        }
        __syncthreads();
        if (tid < 128) {
            sm_l[tid] = sm_l[tid] * sm_scl[tid]
                      + sm_stat[tid * 4 + 0] + sm_stat[tid * 4 + 1]
                      + sm_stat[tid * 4 + 2] + sm_stat[tid * 4 + 3];
        }

        // ---- O rescale + PV --------------------------------------------
        {
            const int orow0 = wid * 16 + (lane >> 2);
            const float s0 = sm_scl[orow0];
            const float s1 = sm_scl[orow0 + 8];
#pragma unroll
            for (int nn = 0; nn < 8; nn++) {
                O[nn][0] *= s0; O[nn][1] *= s0;
                O[nn][2] *= s1; O[nn][3] *= s1;
            }
        }
        CP_WAIT0();
        __syncthreads();

#pragma unroll
        for (int ks = 0; ks < 16; ks++) {
            const int chunk = ks >> 3;
            const int k0b = (ks & 7) * 32;
            uint32_t Ph4[4], Pl4[4];
            const int rowa = wid * 16 + (lane & 15);
            const uint32_t cA = (uint32_t)((ks * 32 + ((lane >> 4) << 4)) ^ ((rowa & 7) << 4));
            ldsm_x4(Ph4, sb + FL_PH + (uint32_t)(rowa * 512) + cA);
            ldsm_x4(Pl4, sb + FL_PL + (uint32_t)(rowa * 512) + cA);
            const uint32_t vbase = sb + FL_V + chunk * 32768;
#pragma unroll
            for (int ng = 0; ng < 4; ng++) {
                const int rowb = ng * 16 + (lane & 7) + ((lane & 16) >> 1);
                const uint32_t cB = (uint32_t)((k0b + (((lane >> 3) & 1) << 4)) ^ ((rowb & 7) << 4));
                uint32_t Vh4[4], Vl4[4];
                ldsm_x4(Vh4, vbase + (uint32_t)(rowb * 256) + cB);
                mma_bf16(O[ng * 2 + 0], Ph4, Vh4 + 0);
                mma_bf16(O[ng * 2 + 1], Ph4, Vh4 + 2);
                mma_bf16(O[ng * 2 + 0], Pl4, Vh4 + 0);
                mma_bf16(O[ng * 2 + 1], Pl4, Vh4 + 2);
                ldsm_x4(Vl4, vbase + 16384 + (uint32_t)(rowb * 256) + cB);
                mma_bf16(O[ng * 2 + 0], Ph4, Vl4 + 0);
                mma_bf16(O[ng * 2 + 1], Ph4, Vl4 + 2);
            }
        }
        __syncthreads();
    }

    // ---- epilogue ------------------------------------------------------
    const int r0 = wid * 16 + (lane >> 2);
    const int r1 = r0 + 8;
    const float inv0 = 1.f / sm_l[r0];
    const float inv1 = 1.f / sm_l[r1];
    const int c0 = (lane & 3) * 2;
#pragma unroll
    for (int nn = 0; nn < 8; nn++) {
        const int col = h * HEADV + nn * 8 + c0;
        *(float2*)(ctx + ((size_t)b * SS + i0 + r0) * DVV + col) =
            make_float2(O[nn][0] * inv0, O[nn][1] * inv0);
        *(float2*)(ctx + ((size_t)b * SS + i0 + r1) * DVV + col) =
            make_float2(O[nn][2] * inv1, O[nn][3] * inv1);
    }
}

// ======================= LayerNorm =========================================
__global__ __launch_bounds__(256)
void ln_kernel(const float* __restrict__ res, const float* __restrict__ gamma,
               const float* __restrict__ beta, float* __restrict__ out)
{
    const int row = blockIdx.x;
    const int c = threadIdx.x * 4;
    const float4 v = *(const float4*)(res + (size_t)row * DOUT + c);
    float s  = v.x + v.y + v.z + v.w;
    float s2 = v.x * v.x + v.y * v.y + v.z * v.z + v.w * v.w;
#pragma unroll
    for (int o = 16; o >= 1; o >>= 1) {
        s  += __shfl_xor_sync(0xffffffffu, s,  o);
        s2 += __shfl_xor_sync(0xffffffffu, s2, o);
    }
    __shared__ float sh[8], sh2[8];
    __shared__ float mu_s, inv_s;
    const int w = threadIdx.x >> 5;
    if ((threadIdx.x & 31) == 0) { sh[w] = s; sh2[w] = s2; }
    __syncthreads();
    if (threadIdx.x == 0) {
        float S = 0.f, S2 = 0.f;
#pragma unroll
        for (int i = 0; i < 8; i++) { S += sh[i]; S2 += sh2[i]; }
        const float mu = S * (1.f / DOUT);
        const float var = S2 * (1.f / DOUT) - mu * mu;
        mu_s = mu; inv_s = rsqrtf(var + LN_EPS);
    }
    __syncthreads();
    const float mu = mu_s, inv = inv_s;
    const float4 g  = *(const float4*)(gamma + c);
    const float4 bt = *(const float4*)(beta + c);
    float4 o;
    o.x = (v.x - mu) * inv * g.x + bt.x;
    o.y = (v.y - mu) * inv * g.y + bt.y;
    o.z = (v.z - mu) * inv * g.z + bt.z;
    o.w = (v.w - mu) * inv * g.w + bt.w;
    *(float4*)(out + (size_t)row * DOUT + c) = o;
}

// ===========================================================================
extern "C" void kernel_launch(void* const* d_in, const int* in_sizes, int n_in,
                              void* d_out, int out_size)
{
    const float* x      = (const float*)d_in[0];
    const float* Wq     = (const float*)d_in[1];
    const float* Wk     = (const float*)d_in[2];
    const float* Wcb    = (const float*)d_in[3];
    const float* Wv     = (const float*)d_in[4];
    const float* bv     = (const float*)d_in[5];
    const float* mixing = (const float*)d_in[6];
    const float* Wd     = (const float*)d_in[7];
    const float* bd     = (const float*)d_in[8];
    const float* gamma  = (const float*)d_in[9];
    const float* beta   = (const float*)d_in[10];
    float* out = (float*)d_out;

    float *q, *k, *v, *ctx, *res, *cb, *cbt;
    __nv_bfloat16 *qh, *ql, *kh, *kl, *xh, *xl, *wh, *wl, *vth, *vtl, *cxh, *cxl;
    cudaGetSymbolAddress((void**)&q,      g_q);
    cudaGetSymbolAddress((void**)&k,      g_k);
    cudaGetSymbolAddress((void**)&v,      g_v);
    cudaGetSymbolAddress((void**)&ctx,    g_ctx);
    cudaGetSymbolAddress((void**)&res,    g_res);
    cudaGetSymbolAddress((void**)&cb,     g_cb);
    cudaGetSymbolAddress((void**)&cbt,    g_cbt);
    cudaGetSymbolAddress((void**)&qh,     g_qh);
    cudaGetSymbolAddress((void**)&ql,     g_ql);
    cudaGetSymbolAddress((void**)&kh,     g_kh);
    cudaGetSymbolAddress((void**)&kl,     g_kl);
    cudaGetSymbolAddress((void**)&xh,     g_xh);
    cudaGetSymbolAddress((void**)&xl,     g_xl);
    cudaGetSymbolAddress((void**)&wh,     g_wh);
    cudaGetSymbolAddress((void**)&wl,     g_wl);
    cudaGetSymbolAddress((void**)&vth,    g_vth);
    cudaGetSymbolAddress((void**)&vtl,    g_vtl);
    cudaGetSymbolAddress((void**)&cxh,    g_cxh);
    cudaGetSymbolAddress((void**)&cxl,    g_cxl);

    cudaFuncSetAttribute(hmma_nt_kernel,  cudaFuncAttributeMaxDynamicSharedMemorySize, 2 * PJ_STAGE);
    cudaFuncSetAttribute(flash_kernel,    cudaFuncAttributeMaxDynamicSharedMemorySize, FL_SMEM);

    const size_t WSZ = 1024 * 1024;

    // splits
    split_kernel<<<MROWS * DIN / 1024, 256>>>(x, xh, xl);
    split_kernel<<<WSZ / 1024, 256>>>(Wq, wh + 0 * WSZ, wl + 0 * WSZ);
    split_kernel<<<WSZ / 1024, 256>>>(Wk, wh + 1 * WSZ, wl + 1 * WSZ);
    split_kernel<<<WSZ / 1024, 256>>>(Wv, wh + 2 * WSZ, wl + 2 * WSZ);
    split_kernel<<<WSZ / 1024, 256>>>(Wd, wh + 3 * WSZ, wl + 3 * WSZ);

    // projections (HMMA)
    dim3 gProj(DKK / 128, MROWS / 128);    // (8, 32)
    hmma_nt_kernel<<<gProj, 256, 2 * PJ_STAGE>>>(xh, xl, wh + 0 * WSZ, wl + 0 * WSZ, nullptr, nullptr, q, DKK);
    hmma_nt_kernel<<<gProj, 256, 2 * PJ_STAGE>>>(xh, xl, wh + 1 * WSZ, wl + 1 * WSZ, nullptr, nullptr, k, DKK);
    hmma_nt_kernel<<<gProj, 256, 2 * PJ_STAGE>>>(xh, xl, wh + 2 * WSZ, wl + 2 * WSZ, bv, nullptr, v, DVV);
    gemm_nt_kernel<<<dim3(1, MROWS / 64), 256>>>(x, Wcb, cb, MROWS, HH, DIN);

    // attention preps
    split_kernel<<<MROWS * DKK / 1024, 256>>>(k, kh, kl);
    prep_q_kernel<<<dim3(SS * DKK / 4 / 256, BH), 256>>>(q, mixing, qh, ql);
    prep_vt_kernel<<<dim3(SS / 64, HEADV / 16, BH), 256>>>(v, vth, vtl);
    cbt_kernel<<<dim3(SS / 256, BH), 256>>>(cb, cbt);

    // fused attention (QK^T + softmax + PV)
    flash_kernel<<<dim3(SS / 128, BH), 256, FL_SMEM>>>(qh, ql, kh, kl, cbt, vth, vtl, ctx);

    // output projection + residual + LN
    split_kernel<<<MROWS * DVV / 1024, 256>>>(ctx, cxh, cxl);
    hmma_nt_kernel<<<gProj, 256, 2 * PJ_STAGE>>>(cxh, cxl, wh + 3 * WSZ, wl + 3 * WSZ, bd, x, res, DOUT);
    ln_kernel<<<MROWS, 256>>>(res, gamma, beta, out);
}